// round 12
// baseline (speedup 1.0000x reference)
#include <cuda_runtime.h>
#include <cuda_bf16.h>
#include <mma.h>
#include <cstdint>

using namespace nvcuda;

#define N_NODES 40000
#define D_IN    512
#define D_OUT   128
#define N_EDGES 640000
#define CAP     64      // slots per row bucket; P(degree>64) ~ 2e-22 for Poisson(16)

#define N_PAD   40064   // 313 CTAs * 128 rows — lets fragment stores run past 40000

// Device scratch (no allocs allowed).
__device__ float4        g_seq[N_PAD * 32];       // seq = X @ W^T (padded), 20.5 MB
__device__ int           g_cnt[N_NODES];          // per-row degree (build cursor)
__device__ uint2         g_edges[N_NODES * CAP];  // packed (col, val) per bucket slot
__device__ __nv_bfloat16 g_wh[D_OUT * D_IN];      // W hi split (bf16), 128 KB
__device__ __nv_bfloat16 g_wl[D_OUT * D_IN];      // W lo split (bf16), 128 KB

// ---------------------------------------------------------------------------
// Pre-split W into bf16 hi/lo ONCE (was redundantly re-converted by all 313
// GEMM CTAs every K-chunk).
// ---------------------------------------------------------------------------
__global__ void wsplit_kernel(const float* __restrict__ w)
{
    int i = blockIdx.x * blockDim.x + threadIdx.x;
    if (i >= D_OUT * D_IN) return;
    float f = w[i];
    __nv_bfloat16 h = __float2bfloat16_rn(f);
    g_wh[i] = h;
    g_wl[i] = __float2bfloat16_rn(f - __bfloat162float(h));
}

// ===========================================================================
// GEMM: seq = X @ W^T via bf16x3 split on WMMA.
// CTA: 128 rows x 128 cols, 512 threads = 16 warps (4x4), warp = 32x32
// sub-tile (2x2 m16n16k16 frags). K loop: 16 chunks of 32, double-buffered
// smem, software-pipelined global loads (prefetch c+1 before MMAs of c).
// A converted f32->bf16 hi/lo in-flight; B copied straight from g_wh/g_wl.
// acc += Ahi*Bhi + Ahi*Blo + Alo*Bhi  (lo*lo ~2^-16 rel, dropped).
// ===========================================================================
#define KC        32
#define LDA       40                     // bf16 elems per row (+8 pad: conflict-free)
#define TILE_ELEM (128 * LDA)            // 5120 bf16 per tile array
#define BUF_ELEM  (4 * TILE_ELEM)        // Ah, Al, Bh, Bl
#define SMEM_GEMM (2 * BUF_ELEM * 2)     // 81920 bytes

__global__ __launch_bounds__(512) void wmma_gemm_kernel(const float* __restrict__ x)
{
    extern __shared__ __nv_bfloat16 sm[];
    const int tid = threadIdx.x;
    const int wid = tid >> 5;
    const int wm  = wid >> 2;            // warp row 0..3
    const int wn  = wid & 3;             // warp col 0..3
    const int blockRow = blockIdx.x * 128;

    // A-load indices: 1024 quads (128 rows x 8 quads), 2 per thread
    const int ra0 = (tid)        >> 3, qa0 = (tid)        & 7;
    const int ra1 = (tid + 512)  >> 3, qa1 = (tid + 512)  & 7;
    // B-load indices: 128 rows x 2 octs (16B = 8 bf16), 1 oct hi + 1 oct lo per thread... 
    // 512 threads cover 128 rows x 4 16B-chunks? 32 bf16/row = 64B = 4 uint4 per row
    const int rb = tid >> 2, qb = tid & 3;

    wmma::fragment<wmma::accumulator, 16, 16, 16, float> acc[2][2];
    #pragma unroll
    for (int mi = 0; mi < 2; mi++)
        #pragma unroll
        for (int ni = 0; ni < 2; ni++) wmma::fill_fragment(acc[mi][ni], 0.f);

    // ---- prefetch chunk 0 ----
    float4 fa0 = make_float4(0.f,0.f,0.f,0.f), fa1 = make_float4(0.f,0.f,0.f,0.f);
    uint4  vbh, vbl;
    {
        int g0 = blockRow + ra0, g1 = blockRow + ra1;
        if (g0 < N_NODES) fa0 = ((const float4*)(x + (size_t)g0 * D_IN))[qa0];
        if (g1 < N_NODES) fa1 = ((const float4*)(x + (size_t)g1 * D_IN))[qa1];
        vbh = *(const uint4*)(g_wh + rb * D_IN + qb * 8);
        vbl = *(const uint4*)(g_wl + rb * D_IN + qb * 8);
    }

    for (int c = 0; c < D_IN / KC; c++) {
        const int b = c & 1;
        __nv_bfloat16* Ah = sm + b * BUF_ELEM;
        __nv_bfloat16* Al = Ah + TILE_ELEM;
        __nv_bfloat16* Bh = Al + TILE_ELEM;
        __nv_bfloat16* Bl = Bh + TILE_ELEM;

        // ---- convert A + store; copy B ----
        {
            float av[8] = {fa0.x, fa0.y, fa0.z, fa0.w, fa1.x, fa1.y, fa1.z, fa1.w};
            uint32_t hp[4], lp[4];
            #pragma unroll
            for (int p = 0; p < 4; p++) {
                __nv_bfloat16 h0 = __float2bfloat16_rn(av[p * 2 + 0]);
                __nv_bfloat16 h1 = __float2bfloat16_rn(av[p * 2 + 1]);
                __nv_bfloat16 l0 = __float2bfloat16_rn(av[p * 2 + 0] - __bfloat162float(h0));
                __nv_bfloat16 l1 = __float2bfloat16_rn(av[p * 2 + 1] - __bfloat162float(h1));
                hp[p] = (uint32_t)__bfloat16_as_ushort(h0) | ((uint32_t)__bfloat16_as_ushort(h1) << 16);
                lp[p] = (uint32_t)__bfloat16_as_ushort(l0) | ((uint32_t)__bfloat16_as_ushort(l1) << 16);
            }
            int e0 = ra0 * LDA + qa0 * 4;
            int e1 = ra1 * LDA + qa1 * 4;
            *(uint2*)(Ah + e0) = make_uint2(hp[0], hp[1]);
            *(uint2*)(Al + e0) = make_uint2(lp[0], lp[1]);
            *(uint2*)(Ah + e1) = make_uint2(hp[2], hp[3]);
            *(uint2*)(Al + e1) = make_uint2(lp[2], lp[3]);

            int eb = rb * LDA + qb * 8;
            *(uint2*)(Bh + eb)     = make_uint2(vbh.x, vbh.y);
            *(uint2*)(Bh + eb + 4) = make_uint2(vbh.z, vbh.w);
            *(uint2*)(Bl + eb)     = make_uint2(vbl.x, vbl.y);
            *(uint2*)(Bl + eb + 4) = make_uint2(vbl.z, vbl.w);
        }
        __syncthreads();

        // ---- prefetch chunk c+1 (overlaps the MMAs below) ----
        if (c + 1 < D_IN / KC) {
            const int kt = (c + 1) * KC;
            int g0 = blockRow + ra0, g1 = blockRow + ra1;
            fa0 = make_float4(0.f,0.f,0.f,0.f);
            fa1 = make_float4(0.f,0.f,0.f,0.f);
            if (g0 < N_NODES) fa0 = ((const float4*)(x + (size_t)g0 * D_IN + kt))[qa0];
            if (g1 < N_NODES) fa1 = ((const float4*)(x + (size_t)g1 * D_IN + kt))[qa1];
            vbh = *(const uint4*)(g_wh + rb * D_IN + kt + qb * 8);
            vbl = *(const uint4*)(g_wl + rb * D_IN + kt + qb * 8);
        }

        // ---- MMAs on buffer b ----
        #pragma unroll
        for (int ks = 0; ks < 2; ks++) {
            const int k0 = ks * 16;
            wmma::fragment<wmma::matrix_a, 16, 16, 16, __nv_bfloat16, wmma::row_major> fah[2], fal[2];
            wmma::fragment<wmma::matrix_b, 16, 16, 16, __nv_bfloat16, wmma::col_major> fbh[2], fbl[2];
            #pragma unroll
            for (int mi = 0; mi < 2; mi++) {
                int r0 = wm * 32 + mi * 16;
                wmma::load_matrix_sync(fah[mi], Ah + r0 * LDA + k0, LDA);
                wmma::load_matrix_sync(fal[mi], Al + r0 * LDA + k0, LDA);
            }
            #pragma unroll
            for (int ni = 0; ni < 2; ni++) {
                int c0 = wn * 32 + ni * 16;
                wmma::load_matrix_sync(fbh[ni], Bh + c0 * LDA + k0, LDA);
                wmma::load_matrix_sync(fbl[ni], Bl + c0 * LDA + k0, LDA);
            }
            #pragma unroll
            for (int mi = 0; mi < 2; mi++)
                #pragma unroll
                for (int ni = 0; ni < 2; ni++) {
                    wmma::mma_sync(acc[mi][ni], fah[mi], fbh[ni], acc[mi][ni]);
                    wmma::mma_sync(acc[mi][ni], fah[mi], fbl[ni], acc[mi][ni]);
                    wmma::mma_sync(acc[mi][ni], fal[mi], fbh[ni], acc[mi][ni]);
                }
        }
    }

    // Epilogue: fragments straight to g_seq (padded to N_PAD rows).
    float* seqf = (float*)g_seq;
    #pragma unroll
    for (int mi = 0; mi < 2; mi++) {
        int row0 = blockRow + wm * 32 + mi * 16;
        #pragma unroll
        for (int ni = 0; ni < 2; ni++) {
            int col0 = wn * 32 + ni * 16;
            wmma::store_matrix_sync(seqf + (size_t)row0 * D_OUT + col0,
                                    acc[mi][ni], D_OUT, wmma::mem_row_major);
        }
    }
}

// ---------------------------------------------------------------------------
// Build step 1: zero counters.
// ---------------------------------------------------------------------------
__global__ void zero_kernel()
{
    int i = blockIdx.x * blockDim.x + threadIdx.x;
    if (i < N_NODES) g_cnt[i] = 0;
}

// ---------------------------------------------------------------------------
// Build step 2: place each edge into its row bucket (combined hist+place).
// ---------------------------------------------------------------------------
__global__ void place_kernel(const float* __restrict__ ev,
                             const int*   __restrict__ er,
                             const int*   __restrict__ ec)
{
    int e = blockIdx.x * blockDim.x + threadIdx.x;
    if (e >= N_EDGES) return;
    int r = er[e];
    int p = atomicAdd(&g_cnt[r], 1);
    if (p < CAP)
        g_edges[r * CAP + p] = make_uint2((unsigned)ec[e], __float_as_uint(ev[e]));
}

// ---------------------------------------------------------------------------
// Gather + bias + PReLU, fused. One warp per node; lane j owns features
// j*4..j*4+3 in registers. Zero atomics. 2-edge unroll for MLP.
// ---------------------------------------------------------------------------
__global__ __launch_bounds__(256) void gather_kernel(const float*  __restrict__ bias,
                                                     const float*  __restrict__ alpha,
                                                     float4*       __restrict__ out)
{
    int gidx = blockIdx.x * blockDim.x + threadIdx.x;
    int node = gidx >> 5;
    int lane = gidx & 31;
    if (node >= N_NODES) return;

    int cnt = g_cnt[node];
    cnt = cnt < CAP ? cnt : CAP;
    const uint2* ep = &g_edges[node * CAP];

    float4 acc = reinterpret_cast<const float4*>(bias)[lane];

    int e = 0;
    for (; e + 1 < cnt; e += 2) {
        uint2 e0 = ep[e];
        uint2 e1 = ep[e + 1];
        float v0 = __uint_as_float(e0.y);
        float v1 = __uint_as_float(e1.y);
        float4 s0 = g_seq[e0.x * 32 + lane];
        float4 s1 = g_seq[e1.x * 32 + lane];
        acc.x = fmaf(v0, s0.x, acc.x);
        acc.y = fmaf(v0, s0.y, acc.y);
        acc.z = fmaf(v0, s0.z, acc.z);
        acc.w = fmaf(v0, s0.w, acc.w);
        acc.x = fmaf(v1, s1.x, acc.x);
        acc.y = fmaf(v1, s1.y, acc.y);
        acc.z = fmaf(v1, s1.z, acc.z);
        acc.w = fmaf(v1, s1.w, acc.w);
    }
    if (e < cnt) {
        uint2 e0 = ep[e];
        float v0 = __uint_as_float(e0.y);
        float4 s0 = g_seq[e0.x * 32 + lane];
        acc.x = fmaf(v0, s0.x, acc.x);
        acc.y = fmaf(v0, s0.y, acc.y);
        acc.z = fmaf(v0, s0.z, acc.z);
        acc.w = fmaf(v0, s0.w, acc.w);
    }

    float a = alpha[0];
    acc.x = acc.x > 0.f ? acc.x : a * acc.x;
    acc.y = acc.y > 0.f ? acc.y : a * acc.y;
    acc.z = acc.z > 0.f ? acc.z : a * acc.z;
    acc.w = acc.w > 0.f ? acc.w : a * acc.w;

    out[node * 32 + lane] = acc;
}

// ---------------------------------------------------------------------------
// Launch. Inputs: x, weight, bias, alpha, edge_val, edge_row, edge_col.
// ---------------------------------------------------------------------------
extern "C" void kernel_launch(void* const* d_in, const int* in_sizes, int n_in,
                              void* d_out, int out_size)
{
    const float* x     = (const float*)d_in[0];
    const float* w     = (const float*)d_in[1];
    const float* bias  = (const float*)d_in[2];
    const float* alpha = (const float*)d_in[3];
    const float* ev    = (const float*)d_in[4];
    const int*   er    = (const int*)  d_in[5];
    const int*   ec    = (const int*)  d_in[6];
    float4*      out   = (float4*)d_out;

    wsplit_kernel<<<(D_OUT * D_IN + 255) / 256, 256>>>(w);

    cudaFuncSetAttribute(wmma_gemm_kernel,
                         cudaFuncAttributeMaxDynamicSharedMemorySize, SMEM_GEMM);
    wmma_gemm_kernel<<<(N_NODES + 127) / 128, 512, SMEM_GEMM>>>(x);

    zero_kernel<<<(N_NODES + 255) / 256, 256>>>();
    place_kernel<<<(N_EDGES + 255) / 256, 256>>>(ev, er, ec);

    {
        long long threads = (long long)N_NODES * 32;
        int blocks = (int)((threads + 255) / 256);
        gather_kernel<<<blocks, 256>>>(bias, alpha, out);
    }
}

// round 13
// speedup vs baseline: 1.2160x; 1.2160x over previous
#include <cuda_runtime.h>
#include <cuda_bf16.h>
#include <mma.h>
#include <cstdint>

using namespace nvcuda;

#define N_NODES 40000
#define D_IN    512
#define D_OUT   128
#define N_EDGES 640000
#define CAP     64      // slots per row bucket; P(degree>64) ~ 2e-22 for Poisson(16)

#define N_PAD   40064

// Device scratch (no allocs allowed).
__device__ float4        g_seq[N_PAD * 32];       // seq = X @ W^T, 20.5 MB
__device__ int           g_cnt[N_NODES];          // per-row degree (build cursor)
__device__ uint2         g_edges[N_NODES * CAP];  // packed (col, val) per bucket slot
__device__ __nv_bfloat16 g_wh[D_OUT * D_IN];      // W hi split (bf16)
__device__ __nv_bfloat16 g_wl[D_OUT * D_IN];      // W lo split (bf16)
__device__ int           g_tile;                  // persistent-CTA tile queue

// ---------------------------------------------------------------------------
// Pre-split W into bf16 hi/lo once + reset the tile queue.
// ---------------------------------------------------------------------------
__global__ void wsplit_kernel(const float* __restrict__ w)
{
    int i = blockIdx.x * blockDim.x + threadIdx.x;
    if (i == 0) g_tile = 0;
    if (i >= D_OUT * D_IN) return;
    float f = w[i];
    __nv_bfloat16 h = __float2bfloat16_rn(f);
    g_wh[i] = h;
    g_wl[i] = __float2bfloat16_rn(f - __bfloat162float(h));
}

// ===========================================================================
// GEMM: seq = X @ W^T via bf16x3 split on WMMA, persistent CTAs.
// Tile: 64 rows x 128 cols (625 tiles, exact). 256 threads = 8 warps (2x4),
// warp = 32x32 (2x2 m16n16k16 frags, 32 acc regs). K: 16 chunks of 32,
// double-buffered smem. __launch_bounds__(256,2) + 61KB smem -> 2 CTAs/SM;
// 296 persistent CTAs pull tiles from g_tile -> balanced waves, small tail.
// acc += Ahi*Bhi + Ahi*Blo + Alo*Bhi  (lo*lo ~2^-16 rel, dropped).
// ===========================================================================
#define KC        32
#define LDA       40                       // bf16 elems per row (+8 pad)
#define TILE_A    (64  * LDA)              // 2560 elems
#define TILE_B    (128 * LDA)              // 5120 elems
#define BUF_ELEM  (2 * TILE_A + 2 * TILE_B)   // Ah, Al, Bh, Bl = 15360 elems
#define SMEM_GEMM (2 * BUF_ELEM * 2)       // 61440 bytes
#define N_TILES   625
#define GEMM_CTAS 296

__global__ __launch_bounds__(256, 2) void wmma_gemm_kernel(const float* __restrict__ x)
{
    extern __shared__ __nv_bfloat16 sm[];
    __shared__ int s_tile;
    const int tid = threadIdx.x;
    const int wid = tid >> 5;
    const int wm  = wid >> 2;              // 0..1: rows wm*32
    const int wn  = wid & 3;               // 0..3: cols wn*32

    // A loads: 64 rows x 8 quads = 512 float4; 2 per thread
    const int ra0 = tid >> 3,         qa0 = tid & 7;
    const int ra1 = (tid + 256) >> 3, qa1 = (tid + 256) & 7;
    // B loads: 128 rows x 4 uint4 = 512 per (hi|lo); 2 each per thread
    const int rb0 = tid >> 2,         qb0 = tid & 3;
    const int rb1 = (tid + 256) >> 2, qb1 = (tid + 256) & 3;

    float* seqf = (float*)g_seq;

    for (;;) {
        if (tid == 0) s_tile = atomicAdd(&g_tile, 1);
        __syncthreads();
        const int tile = s_tile;
        if (tile >= N_TILES) break;
        const int blockRow = tile * 64;    // rows exact: 625*64 = 40000

        wmma::fragment<wmma::accumulator, 16, 16, 16, float> acc[2][2];
        #pragma unroll
        for (int mi = 0; mi < 2; mi++)
            #pragma unroll
            for (int ni = 0; ni < 2; ni++) wmma::fill_fragment(acc[mi][ni], 0.f);

        // prefetch chunk 0
        float4 fa0 = ((const float4*)(x + (size_t)(blockRow + ra0) * D_IN))[qa0];
        float4 fa1 = ((const float4*)(x + (size_t)(blockRow + ra1) * D_IN))[qa1];
        uint4  vh0 = *(const uint4*)(g_wh + rb0 * D_IN + qb0 * 8);
        uint4  vl0 = *(const uint4*)(g_wl + rb0 * D_IN + qb0 * 8);
        uint4  vh1 = *(const uint4*)(g_wh + rb1 * D_IN + qb1 * 8);
        uint4  vl1 = *(const uint4*)(g_wl + rb1 * D_IN + qb1 * 8);

        for (int c = 0; c < D_IN / KC; c++) {
            const int b = c & 1;
            __nv_bfloat16* Ah = sm + b * BUF_ELEM;
            __nv_bfloat16* Al = Ah + TILE_A;
            __nv_bfloat16* Bh = Al + TILE_A;
            __nv_bfloat16* Bl = Bh + TILE_B;

            // convert A hi/lo + store; copy B
            {
                float av[8] = {fa0.x, fa0.y, fa0.z, fa0.w, fa1.x, fa1.y, fa1.z, fa1.w};
                uint32_t hp[4], lp[4];
                #pragma unroll
                for (int p = 0; p < 4; p++) {
                    __nv_bfloat16 h0 = __float2bfloat16_rn(av[p * 2 + 0]);
                    __nv_bfloat16 h1 = __float2bfloat16_rn(av[p * 2 + 1]);
                    __nv_bfloat16 l0 = __float2bfloat16_rn(av[p * 2 + 0] - __bfloat162float(h0));
                    __nv_bfloat16 l1 = __float2bfloat16_rn(av[p * 2 + 1] - __bfloat162float(h1));
                    hp[p] = (uint32_t)__bfloat16_as_ushort(h0) | ((uint32_t)__bfloat16_as_ushort(h1) << 16);
                    lp[p] = (uint32_t)__bfloat16_as_ushort(l0) | ((uint32_t)__bfloat16_as_ushort(l1) << 16);
                }
                int e0 = ra0 * LDA + qa0 * 4;
                int e1 = ra1 * LDA + qa1 * 4;
                *(uint2*)(Ah + e0) = make_uint2(hp[0], hp[1]);
                *(uint2*)(Al + e0) = make_uint2(lp[0], lp[1]);
                *(uint2*)(Ah + e1) = make_uint2(hp[2], hp[3]);
                *(uint2*)(Al + e1) = make_uint2(lp[2], lp[3]);

                int eb0 = rb0 * LDA + qb0 * 8;
                int eb1 = rb1 * LDA + qb1 * 8;
                *(uint2*)(Bh + eb0)     = make_uint2(vh0.x, vh0.y);
                *(uint2*)(Bh + eb0 + 4) = make_uint2(vh0.z, vh0.w);
                *(uint2*)(Bl + eb0)     = make_uint2(vl0.x, vl0.y);
                *(uint2*)(Bl + eb0 + 4) = make_uint2(vl0.z, vl0.w);
                *(uint2*)(Bh + eb1)     = make_uint2(vh1.x, vh1.y);
                *(uint2*)(Bh + eb1 + 4) = make_uint2(vh1.z, vh1.w);
                *(uint2*)(Bl + eb1)     = make_uint2(vl1.x, vl1.y);
                *(uint2*)(Bl + eb1 + 4) = make_uint2(vl1.z, vl1.w);
            }
            __syncthreads();

            // prefetch chunk c+1 (overlaps MMAs)
            if (c + 1 < D_IN / KC) {
                const int kt = (c + 1) * KC;
                fa0 = ((const float4*)(x + (size_t)(blockRow + ra0) * D_IN + kt))[qa0];
                fa1 = ((const float4*)(x + (size_t)(blockRow + ra1) * D_IN + kt))[qa1];
                vh0 = *(const uint4*)(g_wh + rb0 * D_IN + kt + qb0 * 8);
                vl0 = *(const uint4*)(g_wl + rb0 * D_IN + kt + qb0 * 8);
                vh1 = *(const uint4*)(g_wh + rb1 * D_IN + kt + qb1 * 8);
                vl1 = *(const uint4*)(g_wl + rb1 * D_IN + kt + qb1 * 8);
            }

            // MMAs on buffer b
            #pragma unroll
            for (int ks = 0; ks < 2; ks++) {
                const int k0 = ks * 16;
                wmma::fragment<wmma::matrix_a, 16, 16, 16, __nv_bfloat16, wmma::row_major> fah[2], fal[2];
                wmma::fragment<wmma::matrix_b, 16, 16, 16, __nv_bfloat16, wmma::col_major> fbh[2], fbl[2];
                #pragma unroll
                for (int mi = 0; mi < 2; mi++) {
                    int r0 = wm * 32 + mi * 16;
                    wmma::load_matrix_sync(fah[mi], Ah + r0 * LDA + k0, LDA);
                    wmma::load_matrix_sync(fal[mi], Al + r0 * LDA + k0, LDA);
                }
                #pragma unroll
                for (int ni = 0; ni < 2; ni++) {
                    int c0 = wn * 32 + ni * 16;
                    wmma::load_matrix_sync(fbh[ni], Bh + c0 * LDA + k0, LDA);
                    wmma::load_matrix_sync(fbl[ni], Bl + c0 * LDA + k0, LDA);
                }
                #pragma unroll
                for (int mi = 0; mi < 2; mi++)
                    #pragma unroll
                    for (int ni = 0; ni < 2; ni++) {
                        wmma::mma_sync(acc[mi][ni], fah[mi], fbh[ni], acc[mi][ni]);
                        wmma::mma_sync(acc[mi][ni], fah[mi], fbl[ni], acc[mi][ni]);
                        wmma::mma_sync(acc[mi][ni], fal[mi], fbh[ni], acc[mi][ni]);
                    }
            }
        }

        // epilogue straight to g_seq
        #pragma unroll
        for (int mi = 0; mi < 2; mi++) {
            int row0 = blockRow + wm * 32 + mi * 16;
            #pragma unroll
            for (int ni = 0; ni < 2; ni++) {
                int col0 = wn * 32 + ni * 16;
                wmma::store_matrix_sync(seqf + (size_t)row0 * D_OUT + col0,
                                        acc[mi][ni], D_OUT, wmma::mem_row_major);
            }
        }
        // tile-top atomic + __syncthreads serves as the barrier before
        // buffer 0 is overwritten for the next tile.
    }
}

// ---------------------------------------------------------------------------
// Build step 1: zero counters.
// ---------------------------------------------------------------------------
__global__ void zero_kernel()
{
    int i = blockIdx.x * blockDim.x + threadIdx.x;
    if (i < N_NODES) g_cnt[i] = 0;
}

// ---------------------------------------------------------------------------
// Build step 2: place each edge into its row bucket (combined hist+place).
// ---------------------------------------------------------------------------
__global__ void place_kernel(const float* __restrict__ ev,
                             const int*   __restrict__ er,
                             const int*   __restrict__ ec)
{
    int e = blockIdx.x * blockDim.x + threadIdx.x;
    if (e >= N_EDGES) return;
    int r = er[e];
    int p = atomicAdd(&g_cnt[r], 1);
    if (p < CAP)
        g_edges[r * CAP + p] = make_uint2((unsigned)ec[e], __float_as_uint(ev[e]));
}

// ---------------------------------------------------------------------------
// Gather + bias + PReLU, fused. One warp per node; lane j owns features
// j*4..j*4+3 in registers. Zero atomics. 2-edge unroll for MLP.
// ---------------------------------------------------------------------------
__global__ __launch_bounds__(256) void gather_kernel(const float*  __restrict__ bias,
                                                     const float*  __restrict__ alpha,
                                                     float4*       __restrict__ out)
{
    int gidx = blockIdx.x * blockDim.x + threadIdx.x;
    int node = gidx >> 5;
    int lane = gidx & 31;
    if (node >= N_NODES) return;

    int cnt = g_cnt[node];
    cnt = cnt < CAP ? cnt : CAP;
    const uint2* ep = &g_edges[node * CAP];

    float4 acc = reinterpret_cast<const float4*>(bias)[lane];

    int e = 0;
    for (; e + 1 < cnt; e += 2) {
        uint2 e0 = ep[e];
        uint2 e1 = ep[e + 1];
        float v0 = __uint_as_float(e0.y);
        float v1 = __uint_as_float(e1.y);
        float4 s0 = g_seq[e0.x * 32 + lane];
        float4 s1 = g_seq[e1.x * 32 + lane];
        acc.x = fmaf(v0, s0.x, acc.x);
        acc.y = fmaf(v0, s0.y, acc.y);
        acc.z = fmaf(v0, s0.z, acc.z);
        acc.w = fmaf(v0, s0.w, acc.w);
        acc.x = fmaf(v1, s1.x, acc.x);
        acc.y = fmaf(v1, s1.y, acc.y);
        acc.z = fmaf(v1, s1.z, acc.z);
        acc.w = fmaf(v1, s1.w, acc.w);
    }
    if (e < cnt) {
        uint2 e0 = ep[e];
        float v0 = __uint_as_float(e0.y);
        float4 s0 = g_seq[e0.x * 32 + lane];
        acc.x = fmaf(v0, s0.x, acc.x);
        acc.y = fmaf(v0, s0.y, acc.y);
        acc.z = fmaf(v0, s0.z, acc.z);
        acc.w = fmaf(v0, s0.w, acc.w);
    }

    float a = alpha[0];
    acc.x = acc.x > 0.f ? acc.x : a * acc.x;
    acc.y = acc.y > 0.f ? acc.y : a * acc.y;
    acc.z = acc.z > 0.f ? acc.z : a * acc.z;
    acc.w = acc.w > 0.f ? acc.w : a * acc.w;

    out[node * 32 + lane] = acc;
}

// ---------------------------------------------------------------------------
// Launch. Inputs: x, weight, bias, alpha, edge_val, edge_row, edge_col.
// ---------------------------------------------------------------------------
extern "C" void kernel_launch(void* const* d_in, const int* in_sizes, int n_in,
                              void* d_out, int out_size)
{
    const float* x     = (const float*)d_in[0];
    const float* w     = (const float*)d_in[1];
    const float* bias  = (const float*)d_in[2];
    const float* alpha = (const float*)d_in[3];
    const float* ev    = (const float*)d_in[4];
    const int*   er    = (const int*)  d_in[5];
    const int*   ec    = (const int*)  d_in[6];
    float4*      out   = (float4*)d_out;

    wsplit_kernel<<<(D_OUT * D_IN + 255) / 256, 256>>>(w);

    cudaFuncSetAttribute(wmma_gemm_kernel,
                         cudaFuncAttributeMaxDynamicSharedMemorySize, SMEM_GEMM);
    wmma_gemm_kernel<<<GEMM_CTAS, 256, SMEM_GEMM>>>(x);

    zero_kernel<<<(N_NODES + 255) / 256, 256>>>();
    place_kernel<<<(N_EDGES + 255) / 256, 256>>>(ev, er, ec);

    {
        long long threads = (long long)N_NODES * 32;
        int blocks = (int)((threads + 255) / 256);
        gather_kernel<<<blocks, 256>>>(bias, alpha, out);
    }
}

// round 15
// speedup vs baseline: 1.3212x; 1.0865x over previous
#include <cuda_runtime.h>
#include <cuda_bf16.h>
#include <mma.h>
#include <cstdint>

using namespace nvcuda;

#define N_NODES 40000
#define D_IN    512
#define D_OUT   128
#define N_EDGES 640000
#define CAP     64      // slots per row bucket; P(degree>64) ~ 2e-22 for Poisson(16)

#define N_PAD   40064

// Device scratch (no allocs allowed).
__device__ float4        g_seq[N_PAD * 32];       // seq = X @ W^T, 20.5 MB
__device__ int           g_cnt[N_NODES];          // per-row degree (build cursor)
__device__ uint2         g_edges[N_NODES * CAP];  // packed (col, val) per bucket slot
__device__ __nv_bfloat16 g_wh[D_OUT * D_IN];      // W hi split (bf16)
__device__ __nv_bfloat16 g_wl[D_OUT * D_IN];      // W lo split (bf16)
__device__ int           g_tile;                  // persistent-CTA work queue

// ---------------------------------------------------------------------------
// Prep: split W into bf16 hi/lo, zero g_cnt, reset work queue.
// Grid: 256 blocks x 256 = 65536 threads = D_OUT*D_IN exactly.
// ---------------------------------------------------------------------------
__global__ void prep_kernel(const float* __restrict__ w)
{
    int i = blockIdx.x * blockDim.x + threadIdx.x;
    if (i == 0) g_tile = 0;
    if (i < N_NODES) g_cnt[i] = 0;
    float f = w[i];
    __nv_bfloat16 h = __float2bfloat16_rn(f);
    g_wh[i] = h;
    g_wl[i] = __float2bfloat16_rn(f - __bfloat162float(h));
}

// ===========================================================================
// Fused persistent kernel: work queue = 80 edge-place chunks (8000 edges
// each) followed by 625 GEMM tiles (64 rows x 128 cols). Place work is
// independent of GEMM and hides entirely under the tensor-bound phase.
//
// GEMM: seq = X @ W^T via bf16x3 split on WMMA. 256 threads = 8 warps (2x4),
// warp = 32x32 (2x2 m16n16k16 frags). K: 16 chunks of 32, double-buffered
// smem. __launch_bounds__(256,2) + 61KB smem -> 2 CTAs/SM.
// acc += Ahi*Bhi + Ahi*Blo + Alo*Bhi  (lo*lo ~2^-16 rel, dropped).
// ===========================================================================
#define KC        32
#define LDA       40                          // bf16 elems per row (+8 pad)
#define TILE_A    (64  * LDA)                 // 2560 elems
#define TILE_B    (128 * LDA)                 // 5120 elems
#define BUF_ELEM  (2 * TILE_A + 2 * TILE_B)   // 15360 elems
#define SMEM_GEMM (2 * BUF_ELEM * 2)          // 61440 bytes
#define N_TILES      625
#define PLACE_CHUNKS 80
#define EDGES_PER_CH (N_EDGES / PLACE_CHUNKS) // 8000
#define N_ITEMS      (PLACE_CHUNKS + N_TILES)
#define GEMM_CTAS    296

__global__ __launch_bounds__(256, 2) void fused_kernel(const float* __restrict__ x,
                                                       const float* __restrict__ ev,
                                                       const int*   __restrict__ er,
                                                       const int*   __restrict__ ec)
{
    extern __shared__ __nv_bfloat16 sm[];
    __shared__ int s_item;
    const int tid = threadIdx.x;
    const int wid = tid >> 5;
    const int wm  = wid >> 2;              // 0..1: rows wm*32
    const int wn  = wid & 3;               // 0..3: cols wn*32

    // A loads: 64 rows x 8 quads = 512 float4; 2 per thread
    const int ra0 = tid >> 3,         qa0 = tid & 7;
    const int ra1 = (tid + 256) >> 3, qa1 = (tid + 256) & 7;
    // B loads: 128 rows x 4 uint4 per (hi|lo); 2 each per thread
    const int rb0 = tid >> 2,         qb0 = tid & 3;
    const int rb1 = (tid + 256) >> 2, qb1 = (tid + 256) & 3;

    float* seqf = (float*)g_seq;

    for (;;) {
        if (tid == 0) s_item = atomicAdd(&g_tile, 1);
        __syncthreads();
        const int item = s_item;
        if (item >= N_ITEMS) break;

        if (item < PLACE_CHUNKS) {
            // ---- edge placement chunk: 8000 edges, 256 threads ----
            const int e0 = item * EDGES_PER_CH;
            const int e1 = e0 + EDGES_PER_CH;
            for (int e = e0 + tid; e < e1; e += 256) {
                int r = er[e];
                int p = atomicAdd(&g_cnt[r], 1);
                if (p < CAP)
                    g_edges[r * CAP + p] =
                        make_uint2((unsigned)ec[e], __float_as_uint(ev[e]));
            }
            continue;
        }

        // ---- GEMM tile ----
        const int blockRow = (item - PLACE_CHUNKS) * 64;   // 625*64 = 40000 exact

        wmma::fragment<wmma::accumulator, 16, 16, 16, float> acc[2][2];
        #pragma unroll
        for (int mi = 0; mi < 2; mi++)
            #pragma unroll
            for (int ni = 0; ni < 2; ni++) wmma::fill_fragment(acc[mi][ni], 0.f);

        // prefetch chunk 0
        float4 fa0 = ((const float4*)(x + (size_t)(blockRow + ra0) * D_IN))[qa0];
        float4 fa1 = ((const float4*)(x + (size_t)(blockRow + ra1) * D_IN))[qa1];
        uint4  vh0 = *(const uint4*)(g_wh + rb0 * D_IN + qb0 * 8);
        uint4  vl0 = *(const uint4*)(g_wl + rb0 * D_IN + qb0 * 8);
        uint4  vh1 = *(const uint4*)(g_wh + rb1 * D_IN + qb1 * 8);
        uint4  vl1 = *(const uint4*)(g_wl + rb1 * D_IN + qb1 * 8);

        for (int c = 0; c < D_IN / KC; c++) {
            const int b = c & 1;
            __nv_bfloat16* Ah = sm + b * BUF_ELEM;
            __nv_bfloat16* Al = Ah + TILE_A;
            __nv_bfloat16* Bh = Al + TILE_A;
            __nv_bfloat16* Bl = Bh + TILE_B;

            // convert A hi/lo + store; copy B
            {
                float av[8] = {fa0.x, fa0.y, fa0.z, fa0.w, fa1.x, fa1.y, fa1.z, fa1.w};
                uint32_t hp[4], lp[4];
                #pragma unroll
                for (int p = 0; p < 4; p++) {
                    __nv_bfloat16 h0 = __float2bfloat16_rn(av[p * 2 + 0]);
                    __nv_bfloat16 h1 = __float2bfloat16_rn(av[p * 2 + 1]);
                    __nv_bfloat16 l0 = __float2bfloat16_rn(av[p * 2 + 0] - __bfloat162float(h0));
                    __nv_bfloat16 l1 = __float2bfloat16_rn(av[p * 2 + 1] - __bfloat162float(h1));
                    hp[p] = (uint32_t)__bfloat16_as_ushort(h0) | ((uint32_t)__bfloat16_as_ushort(h1) << 16);
                    lp[p] = (uint32_t)__bfloat16_as_ushort(l0) | ((uint32_t)__bfloat16_as_ushort(l1) << 16);
                }
                int ea0 = ra0 * LDA + qa0 * 4;
                int ea1 = ra1 * LDA + qa1 * 4;
                *(uint2*)(Ah + ea0) = make_uint2(hp[0], hp[1]);
                *(uint2*)(Al + ea0) = make_uint2(lp[0], lp[1]);
                *(uint2*)(Ah + ea1) = make_uint2(hp[2], hp[3]);
                *(uint2*)(Al + ea1) = make_uint2(lp[2], lp[3]);

                int eb0 = rb0 * LDA + qb0 * 8;
                int eb1 = rb1 * LDA + qb1 * 8;
                *(uint2*)(Bh + eb0)     = make_uint2(vh0.x, vh0.y);
                *(uint2*)(Bh + eb0 + 4) = make_uint2(vh0.z, vh0.w);
                *(uint2*)(Bl + eb0)     = make_uint2(vl0.x, vl0.y);
                *(uint2*)(Bl + eb0 + 4) = make_uint2(vl0.z, vl0.w);
                *(uint2*)(Bh + eb1)     = make_uint2(vh1.x, vh1.y);
                *(uint2*)(Bh + eb1 + 4) = make_uint2(vh1.z, vh1.w);
                *(uint2*)(Bl + eb1)     = make_uint2(vl1.x, vl1.y);
                *(uint2*)(Bl + eb1 + 4) = make_uint2(vl1.z, vl1.w);
            }
            __syncthreads();

            // prefetch chunk c+1 (overlaps MMAs)
            if (c + 1 < D_IN / KC) {
                const int kt = (c + 1) * KC;
                fa0 = ((const float4*)(x + (size_t)(blockRow + ra0) * D_IN + kt))[qa0];
                fa1 = ((const float4*)(x + (size_t)(blockRow + ra1) * D_IN + kt))[qa1];
                vh0 = *(const uint4*)(g_wh + rb0 * D_IN + kt + qb0 * 8);
                vl0 = *(const uint4*)(g_wl + rb0 * D_IN + kt + qb0 * 8);
                vh1 = *(const uint4*)(g_wh + rb1 * D_IN + kt + qb1 * 8);
                vl1 = *(const uint4*)(g_wl + rb1 * D_IN + kt + qb1 * 8);
            }

            // MMAs on buffer b
            #pragma unroll
            for (int ks = 0; ks < 2; ks++) {
                const int k0 = ks * 16;
                wmma::fragment<wmma::matrix_a, 16, 16, 16, __nv_bfloat16, wmma::row_major> fah[2], fal[2];
                wmma::fragment<wmma::matrix_b, 16, 16, 16, __nv_bfloat16, wmma::col_major> fbh[2], fbl[2];
                #pragma unroll
                for (int mi = 0; mi < 2; mi++) {
                    int r0 = wm * 32 + mi * 16;
                    wmma::load_matrix_sync(fah[mi], Ah + r0 * LDA + k0, LDA);
                    wmma::load_matrix_sync(fal[mi], Al + r0 * LDA + k0, LDA);
                }
                #pragma unroll
                for (int ni = 0; ni < 2; ni++) {
                    int c0 = wn * 32 + ni * 16;
                    wmma::load_matrix_sync(fbh[ni], Bh + c0 * LDA + k0, LDA);
                    wmma::load_matrix_sync(fbl[ni], Bl + c0 * LDA + k0, LDA);
                }
                #pragma unroll
                for (int mi = 0; mi < 2; mi++)
                    #pragma unroll
                    for (int ni = 0; ni < 2; ni++) {
                        wmma::mma_sync(acc[mi][ni], fah[mi], fbh[ni], acc[mi][ni]);
                        wmma::mma_sync(acc[mi][ni], fah[mi], fbl[ni], acc[mi][ni]);
                        wmma::mma_sync(acc[mi][ni], fal[mi], fbh[ni], acc[mi][ni]);
                    }
            }
        }

        // epilogue straight to g_seq
        #pragma unroll
        for (int mi = 0; mi < 2; mi++) {
            int row0 = blockRow + wm * 32 + mi * 16;
            #pragma unroll
            for (int ni = 0; ni < 2; ni++) {
                int col0 = wn * 32 + ni * 16;
                wmma::store_matrix_sync(seqf + (size_t)row0 * D_OUT + col0,
                                        acc[mi][ni], D_OUT, wmma::mem_row_major);
            }
        }
        // item-top atomic + __syncthreads is the barrier before smem reuse.
    }
}

// ---------------------------------------------------------------------------
// Gather + bias + PReLU, fused. One warp per node; lane j owns features
// j*4..j*4+3 in registers. Zero atomics. 2-edge unroll for MLP.
// ---------------------------------------------------------------------------
__global__ __launch_bounds__(256) void gather_kernel(const float*  __restrict__ bias,
                                                     const float*  __restrict__ alpha,
                                                     float4*       __restrict__ out)
{
    int gidx = blockIdx.x * blockDim.x + threadIdx.x;
    int node = gidx >> 5;
    int lane = gidx & 31;
    if (node >= N_NODES) return;

    int cnt = g_cnt[node];
    cnt = cnt < CAP ? cnt : CAP;
    const uint2* ep = &g_edges[node * CAP];

    float4 acc = reinterpret_cast<const float4*>(bias)[lane];

    int e = 0;
    for (; e + 1 < cnt; e += 2) {
        uint2 e0 = ep[e];
        uint2 e1 = ep[e + 1];
        float v0 = __uint_as_float(e0.y);
        float v1 = __uint_as_float(e1.y);
        float4 s0 = g_seq[e0.x * 32 + lane];
        float4 s1 = g_seq[e1.x * 32 + lane];
        acc.x = fmaf(v0, s0.x, acc.x);
        acc.y = fmaf(v0, s0.y, acc.y);
        acc.z = fmaf(v0, s0.z, acc.z);
        acc.w = fmaf(v0, s0.w, acc.w);
        acc.x = fmaf(v1, s1.x, acc.x);
        acc.y = fmaf(v1, s1.y, acc.y);
        acc.z = fmaf(v1, s1.z, acc.z);
        acc.w = fmaf(v1, s1.w, acc.w);
    }
    if (e < cnt) {
        uint2 e0 = ep[e];
        float v0 = __uint_as_float(e0.y);
        float4 s0 = g_seq[e0.x * 32 + lane];
        acc.x = fmaf(v0, s0.x, acc.x);
        acc.y = fmaf(v0, s0.y, acc.y);
        acc.z = fmaf(v0, s0.z, acc.z);
        acc.w = fmaf(v0, s0.w, acc.w);
    }

    float a = alpha[0];
    acc.x = acc.x > 0.f ? acc.x : a * acc.x;
    acc.y = acc.y > 0.f ? acc.y : a * acc.y;
    acc.z = acc.z > 0.f ? acc.z : a * acc.z;
    acc.w = acc.w > 0.f ? acc.w : a * acc.w;

    out[node * 32 + lane] = acc;
}

// ---------------------------------------------------------------------------
// Launch. Inputs: x, weight, bias, alpha, edge_val, edge_row, edge_col.
// ---------------------------------------------------------------------------
extern "C" void kernel_launch(void* const* d_in, const int* in_sizes, int n_in,
                              void* d_out, int out_size)
{
    const float* x     = (const float*)d_in[0];
    const float* w     = (const float*)d_in[1];
    const float* bias  = (const float*)d_in[2];
    const float* alpha = (const float*)d_in[3];
    const float* ev    = (const float*)d_in[4];
    const int*   er    = (const int*)  d_in[5];
    const int*   ec    = (const int*)  d_in[6];
    float4*      out   = (float4*)d_out;

    // 65536 threads = D_OUT*D_IN exactly; also zeroes g_cnt + queue.
    prep_kernel<<<256, 256>>>(w);

    cudaFuncSetAttribute(fused_kernel,
                         cudaFuncAttributeMaxDynamicSharedMemorySize, SMEM_GEMM);
    fused_kernel<<<GEMM_CTAS, 256, SMEM_GEMM>>>(x, ev, er, ec);

    {
        long long threads = (long long)N_NODES * 32;
        int blocks = (int)((threads + 255) / 256);
        gather_kernel<<<blocks, 256>>>(bias, alpha, out);
    }
}

// round 16
// speedup vs baseline: 1.3712x; 1.0379x over previous
#include <cuda_runtime.h>
#include <cuda_bf16.h>
#include <mma.h>
#include <cstdint>

using namespace nvcuda;

#define N_NODES 40000
#define D_IN    512
#define D_OUT   128
#define N_EDGES 640000
#define CAP     64      // slots per row bucket; P(degree>64) ~ 2e-22 for Poisson(16)

#define N_PAD   40064

// Device scratch (no allocs allowed).
__device__ float4        g_seq[N_PAD * 32];       // seq = X @ W^T, 20.5 MB
__device__ int           g_cnt[N_NODES];          // per-row degree (build cursor)
__device__ uint2         g_edges[N_NODES * CAP];  // packed (col, val) per bucket slot
__device__ __nv_bfloat16 g_wh[D_OUT * D_IN];      // W hi split (bf16)
__device__ __nv_bfloat16 g_wl[D_OUT * D_IN];      // W lo split (bf16)
__device__ int           g_tile;                  // persistent-CTA work queue

// ---------------------------------------------------------------------------
// Prep: split W to bf16 hi/lo, zero g_cnt, zero g_seq tail rows (37888..39999,
// accumulated via red.add by K-split tiles), reset work queue.
// Grid: 1056 x 256 = 270336 threads = 2112 rows * 128 cols exactly.
// ---------------------------------------------------------------------------
#define QROW0 37888                       // first row owned by K-split tiles

__global__ void prep_kernel(const float* __restrict__ w)
{
    int i = blockIdx.x * blockDim.x + threadIdx.x;
    if (i == 0) g_tile = 0;
    if (i < N_NODES) g_cnt[i] = 0;
    if (i < D_OUT * D_IN) {
        float f = w[i];
        __nv_bfloat16 h = __float2bfloat16_rn(f);
        g_wh[i] = h;
        g_wl[i] = __float2bfloat16_rn(f - __bfloat162float(h));
    }
    ((float*)g_seq)[(size_t)QROW0 * D_OUT + i] = 0.f;   // 270336 = 2112*128 exact
}

// ===========================================================================
// Fused persistent kernel. Work queue (in order):
//   [0, 80)        edge-place chunks (8000 edges each; independent of GEMM)
//   [80, 672)      592 full GEMM tiles, 64 rows x 128 cols (rows 0..37887)
//                  -> 2 * 296 CTA slots: perfectly quantized
//   [672, 804)     132 K-split quarter tiles (33 row-blocks x 4 K-pieces of
//                  K=128) covering rows 37888..39999; ~1/4 cost each, they
//                  fill the makespan tail; results red.add into zeroed g_seq.
//
// GEMM: seq = X @ W^T via bf16x3 split on WMMA. 256 threads = 8 warps (2x4),
// warp = 32x32 (2x2 m16n16k16 frags). K chunks of 32, double-buffered smem.
// __launch_bounds__(256,2) + 61KB smem -> 2 CTAs/SM.
// acc += Ahi*Bhi + Ahi*Blo + Alo*Bhi  (lo*lo ~2^-16 rel, dropped).
// ===========================================================================
#define KC        32
#define LDA       40                          // bf16 elems per row (+8 pad)
#define TILE_A    (64  * LDA)                 // 2560 elems
#define TILE_B    (128 * LDA)                 // 5120 elems
#define BUF_ELEM  (2 * TILE_A + 2 * TILE_B)   // 15360 elems
#define SMEM_GEMM (2 * BUF_ELEM * 2)          // 61440 bytes
#define PLACE_CHUNKS 80
#define EDGES_PER_CH (N_EDGES / PLACE_CHUNKS) // 8000
#define N_FULL       592
#define N_QITEMS     132                      // 33 row-blocks * 4 K-pieces
#define N_ITEMS      (PLACE_CHUNKS + N_FULL + N_QITEMS)
#define GEMM_CTAS    296

__global__ __launch_bounds__(256, 2) void fused_kernel(const float* __restrict__ x,
                                                       const float* __restrict__ ev,
                                                       const int*   __restrict__ er,
                                                       const int*   __restrict__ ec)
{
    extern __shared__ __nv_bfloat16 sm[];
    __shared__ int s_item;
    const int tid = threadIdx.x;
    const int wid = tid >> 5;
    const int wm  = wid >> 2;              // 0..1: rows wm*32
    const int wn  = wid & 3;               // 0..3: cols wn*32

    // A loads: 64 rows x 8 quads = 512 float4; 2 per thread
    const int ra0 = tid >> 3,         qa0 = tid & 7;
    const int ra1 = (tid + 256) >> 3, qa1 = (tid + 256) & 7;
    // B loads: 128 rows x 4 uint4 per (hi|lo); 2 each per thread
    const int rb0 = tid >> 2,         qb0 = tid & 3;
    const int rb1 = (tid + 256) >> 2, qb1 = (tid + 256) & 3;

    float* seqf = (float*)g_seq;

    for (;;) {
        if (tid == 0) s_item = atomicAdd(&g_tile, 1);
        __syncthreads();
        const int item = s_item;
        if (item >= N_ITEMS) break;

        if (item < PLACE_CHUNKS) {
            // ---- edge placement chunk ----
            const int e0 = item * EDGES_PER_CH;
            const int e1 = e0 + EDGES_PER_CH;
            for (int e = e0 + tid; e < e1; e += 256) {
                int r = er[e];
                int p = atomicAdd(&g_cnt[r], 1);
                if (p < CAP)
                    g_edges[r * CAP + p] =
                        make_uint2((unsigned)ec[e], __float_as_uint(ev[e]));
            }
            continue;
        }

        // ---- GEMM tile (full or K-split quarter) ----
        int blockRow, c0, c1;
        bool partial;
        if (item < PLACE_CHUNKS + N_FULL) {
            blockRow = (item - PLACE_CHUNKS) * 64;          // rows 0..37887
            c0 = 0; c1 = D_IN / KC;                          // 16 chunks
            partial = false;
        } else {
            int q     = item - PLACE_CHUNKS - N_FULL;        // 0..131
            blockRow  = QROW0 + (q >> 2) * 64;               // rows 37888..39999
            c0        = (q & 3) * 4;                         // 4 chunks (K=128)
            c1        = c0 + 4;
            partial   = true;
        }

        wmma::fragment<wmma::accumulator, 16, 16, 16, float> acc[2][2];
        #pragma unroll
        for (int mi = 0; mi < 2; mi++)
            #pragma unroll
            for (int ni = 0; ni < 2; ni++) wmma::fill_fragment(acc[mi][ni], 0.f);

        // prefetch first chunk
        {
            const int kt = c0 * KC;
            // (declarations below)
        }
        float4 fa0, fa1;
        uint4  vh0, vl0, vh1, vl1;
        {
            const int kt = c0 * KC;
            fa0 = ((const float4*)(x + (size_t)(blockRow + ra0) * D_IN + kt))[qa0];
            fa1 = ((const float4*)(x + (size_t)(blockRow + ra1) * D_IN + kt))[qa1];
            vh0 = *(const uint4*)(g_wh + rb0 * D_IN + kt + qb0 * 8);
            vl0 = *(const uint4*)(g_wl + rb0 * D_IN + kt + qb0 * 8);
            vh1 = *(const uint4*)(g_wh + rb1 * D_IN + kt + qb1 * 8);
            vl1 = *(const uint4*)(g_wl + rb1 * D_IN + kt + qb1 * 8);
        }

        for (int c = c0; c < c1; c++) {
            const int b = c & 1;
            __nv_bfloat16* Ah = sm + b * BUF_ELEM;
            __nv_bfloat16* Al = Ah + TILE_A;
            __nv_bfloat16* Bh = Al + TILE_A;
            __nv_bfloat16* Bl = Bh + TILE_B;

            // convert A hi/lo + store; copy B
            {
                float av[8] = {fa0.x, fa0.y, fa0.z, fa0.w, fa1.x, fa1.y, fa1.z, fa1.w};
                uint32_t hp[4], lp[4];
                #pragma unroll
                for (int p = 0; p < 4; p++) {
                    __nv_bfloat16 h0 = __float2bfloat16_rn(av[p * 2 + 0]);
                    __nv_bfloat16 h1 = __float2bfloat16_rn(av[p * 2 + 1]);
                    __nv_bfloat16 l0 = __float2bfloat16_rn(av[p * 2 + 0] - __bfloat162float(h0));
                    __nv_bfloat16 l1 = __float2bfloat16_rn(av[p * 2 + 1] - __bfloat162float(h1));
                    hp[p] = (uint32_t)__bfloat16_as_ushort(h0) | ((uint32_t)__bfloat16_as_ushort(h1) << 16);
                    lp[p] = (uint32_t)__bfloat16_as_ushort(l0) | ((uint32_t)__bfloat16_as_ushort(l1) << 16);
                }
                int ea0 = ra0 * LDA + qa0 * 4;
                int ea1 = ra1 * LDA + qa1 * 4;
                *(uint2*)(Ah + ea0) = make_uint2(hp[0], hp[1]);
                *(uint2*)(Al + ea0) = make_uint2(lp[0], lp[1]);
                *(uint2*)(Ah + ea1) = make_uint2(hp[2], hp[3]);
                *(uint2*)(Al + ea1) = make_uint2(lp[2], lp[3]);

                int eb0 = rb0 * LDA + qb0 * 8;
                int eb1 = rb1 * LDA + qb1 * 8;
                *(uint2*)(Bh + eb0)     = make_uint2(vh0.x, vh0.y);
                *(uint2*)(Bh + eb0 + 4) = make_uint2(vh0.z, vh0.w);
                *(uint2*)(Bl + eb0)     = make_uint2(vl0.x, vl0.y);
                *(uint2*)(Bl + eb0 + 4) = make_uint2(vl0.z, vl0.w);
                *(uint2*)(Bh + eb1)     = make_uint2(vh1.x, vh1.y);
                *(uint2*)(Bh + eb1 + 4) = make_uint2(vh1.z, vh1.w);
                *(uint2*)(Bl + eb1)     = make_uint2(vl1.x, vl1.y);
                *(uint2*)(Bl + eb1 + 4) = make_uint2(vl1.z, vl1.w);
            }
            __syncthreads();

            // prefetch next chunk (overlaps MMAs)
            if (c + 1 < c1) {
                const int kt = (c + 1) * KC;
                fa0 = ((const float4*)(x + (size_t)(blockRow + ra0) * D_IN + kt))[qa0];
                fa1 = ((const float4*)(x + (size_t)(blockRow + ra1) * D_IN + kt))[qa1];
                vh0 = *(const uint4*)(g_wh + rb0 * D_IN + kt + qb0 * 8);
                vl0 = *(const uint4*)(g_wl + rb0 * D_IN + kt + qb0 * 8);
                vh1 = *(const uint4*)(g_wh + rb1 * D_IN + kt + qb1 * 8);
                vl1 = *(const uint4*)(g_wl + rb1 * D_IN + kt + qb1 * 8);
            }

            // MMAs on buffer b
            #pragma unroll
            for (int ks = 0; ks < 2; ks++) {
                const int k0 = ks * 16;
                wmma::fragment<wmma::matrix_a, 16, 16, 16, __nv_bfloat16, wmma::row_major> fah[2], fal[2];
                wmma::fragment<wmma::matrix_b, 16, 16, 16, __nv_bfloat16, wmma::col_major> fbh[2], fbl[2];
                #pragma unroll
                for (int mi = 0; mi < 2; mi++) {
                    int r0 = wm * 32 + mi * 16;
                    wmma::load_matrix_sync(fah[mi], Ah + r0 * LDA + k0, LDA);
                    wmma::load_matrix_sync(fal[mi], Al + r0 * LDA + k0, LDA);
                }
                #pragma unroll
                for (int ni = 0; ni < 2; ni++) {
                    int cc = wn * 32 + ni * 16;
                    wmma::load_matrix_sync(fbh[ni], Bh + cc * LDA + k0, LDA);
                    wmma::load_matrix_sync(fbl[ni], Bl + cc * LDA + k0, LDA);
                }
                #pragma unroll
                for (int mi = 0; mi < 2; mi++)
                    #pragma unroll
                    for (int ni = 0; ni < 2; ni++) {
                        wmma::mma_sync(acc[mi][ni], fah[mi], fbh[ni], acc[mi][ni]);
                        wmma::mma_sync(acc[mi][ni], fah[mi], fbl[ni], acc[mi][ni]);
                        wmma::mma_sync(acc[mi][ni], fal[mi], fbh[ni], acc[mi][ni]);
                    }
            }
        }

        if (!partial) {
            // epilogue: fragments straight to g_seq
            #pragma unroll
            for (int mi = 0; mi < 2; mi++) {
                int row0 = blockRow + wm * 32 + mi * 16;
                #pragma unroll
                for (int ni = 0; ni < 2; ni++) {
                    int col0 = wn * 32 + ni * 16;
                    wmma::store_matrix_sync(seqf + (size_t)row0 * D_OUT + col0,
                                            acc[mi][ni], D_OUT, wmma::mem_row_major);
                }
            }
        } else {
            // epilogue: frags -> smem f32 tile -> red.global.add into g_seq
            float* sacc = (float*)sm;                 // 64x128 f32 = 32 KB
            __syncthreads();                          // all MMA smem reads done
            #pragma unroll
            for (int mi = 0; mi < 2; mi++) {
                int r0 = wm * 32 + mi * 16;
                #pragma unroll
                for (int ni = 0; ni < 2; ni++) {
                    int cc = wn * 32 + ni * 16;
                    wmma::store_matrix_sync(sacc + r0 * D_OUT + cc,
                                            acc[mi][ni], D_OUT, wmma::mem_row_major);
                }
            }
            __syncthreads();
            #pragma unroll
            for (int i = 0; i < 8; i++) {             // 2048 float4 / 256 thr
                int idx = i * 256 + tid;
                float4 v = ((const float4*)sacc)[idx];
                float* o = seqf + ((size_t)blockRow + (idx >> 5)) * D_OUT + (idx & 31) * 4;
                asm volatile("red.global.add.v4.f32 [%0], {%1, %2, %3, %4};"
                             :: "l"(o), "f"(v.x), "f"(v.y), "f"(v.z), "f"(v.w)
                             : "memory");
            }
        }
        // item-top atomic + __syncthreads is the barrier before smem reuse.
    }
}

// ---------------------------------------------------------------------------
// Gather + bias + PReLU, fused. One warp per node; lane j owns features
// j*4..j*4+3 in registers. Zero atomics. 2-edge unroll for MLP.
// ---------------------------------------------------------------------------
__global__ __launch_bounds__(256) void gather_kernel(const float*  __restrict__ bias,
                                                     const float*  __restrict__ alpha,
                                                     float4*       __restrict__ out)
{
    int gidx = blockIdx.x * blockDim.x + threadIdx.x;
    int node = gidx >> 5;
    int lane = gidx & 31;
    if (node >= N_NODES) return;

    int cnt = g_cnt[node];
    cnt = cnt < CAP ? cnt : CAP;
    const uint2* ep = &g_edges[node * CAP];

    float4 acc = reinterpret_cast<const float4*>(bias)[lane];

    int e = 0;
    for (; e + 1 < cnt; e += 2) {
        uint2 e0 = ep[e];
        uint2 e1 = ep[e + 1];
        float v0 = __uint_as_float(e0.y);
        float v1 = __uint_as_float(e1.y);
        float4 s0 = g_seq[e0.x * 32 + lane];
        float4 s1 = g_seq[e1.x * 32 + lane];
        acc.x = fmaf(v0, s0.x, acc.x);
        acc.y = fmaf(v0, s0.y, acc.y);
        acc.z = fmaf(v0, s0.z, acc.z);
        acc.w = fmaf(v0, s0.w, acc.w);
        acc.x = fmaf(v1, s1.x, acc.x);
        acc.y = fmaf(v1, s1.y, acc.y);
        acc.z = fmaf(v1, s1.z, acc.z);
        acc.w = fmaf(v1, s1.w, acc.w);
    }
    if (e < cnt) {
        uint2 e0 = ep[e];
        float v0 = __uint_as_float(e0.y);
        float4 s0 = g_seq[e0.x * 32 + lane];
        acc.x = fmaf(v0, s0.x, acc.x);
        acc.y = fmaf(v0, s0.y, acc.y);
        acc.z = fmaf(v0, s0.z, acc.z);
        acc.w = fmaf(v0, s0.w, acc.w);
    }

    float a = alpha[0];
    acc.x = acc.x > 0.f ? acc.x : a * acc.x;
    acc.y = acc.y > 0.f ? acc.y : a * acc.y;
    acc.z = acc.z > 0.f ? acc.z : a * acc.z;
    acc.w = acc.w > 0.f ? acc.w : a * acc.w;

    out[node * 32 + lane] = acc;
}

// ---------------------------------------------------------------------------
// Launch. Inputs: x, weight, bias, alpha, edge_val, edge_row, edge_col.
// ---------------------------------------------------------------------------
extern "C" void kernel_launch(void* const* d_in, const int* in_sizes, int n_in,
                              void* d_out, int out_size)
{
    const float* x     = (const float*)d_in[0];
    const float* w     = (const float*)d_in[1];
    const float* bias  = (const float*)d_in[2];
    const float* alpha = (const float*)d_in[3];
    const float* ev    = (const float*)d_in[4];
    const int*   er    = (const int*)  d_in[5];
    const int*   ec    = (const int*)  d_in[6];
    float4*      out   = (float4*)d_out;

    // 270336 threads: W split (65536), g_cnt zero (40000), seq tail zero (270336).
    prep_kernel<<<1056, 256>>>(w);

    cudaFuncSetAttribute(fused_kernel,
                         cudaFuncAttributeMaxDynamicSharedMemorySize, SMEM_GEMM);
    fused_kernel<<<GEMM_CTAS, 256, SMEM_GEMM>>>(x, ev, er, ec);

    {
        long long threads = (long long)N_NODES * 32;
        int blocks = (int)((threads + 255) / 256);
        gather_kernel<<<blocks, 256>>>(bias, alpha, out);
    }
}